// round 10
// baseline (speedup 1.0000x reference)
#include <cuda_runtime.h>
#include <cuda_bf16.h>
#include <stdint.h>

#define MAXN 50000
#define MAXE 1600000
#define FEAT 128
#define HID 32
#define NOUT 64
#define CAP 160    // bucket capacity; deg ~ Poisson(32), P(deg>=160) ~ 0

#define T1_BM 256  // rows per block in transform1
#define T1_KC 16   // k-chunk
#define XST 20     // xs row stride (floats): conflict-free for strided ty rows

// Scratch (device globals; allocation is forbidden).
__device__ int    d_is32;                 // 1 if edge_index is int32
__device__ int    d_cnt[MAXN];            // in-degree (no self loop)
__device__ int    d_csr[MAXN * CAP];      // bucketed: src ids for dst=i at [i*CAP ...]
__device__ float  d_dinv[MAXN];           // rsqrt(deg+1)
__device__ float  d_g1[MAXN * HID];       // (x@W1)*dinv
__device__ float  d_g2[MAXN * HID];       // (h1@W2)*dinv

// ---------------------------------------------------------------- init + dtype detect
__global__ void k_init(int N) {
    int i = blockIdx.x * blockDim.x + threadIdx.x;
    if (i < N) d_cnt[i] = 0;
    if (i == 0) d_is32 = 0;
}

// Sample first 64K words: int64 indices < 2^31 have all-zero odd 32-bit words.
__global__ void k_detect(const int* __restrict__ w, int nwords) {
    int i = blockIdx.x * blockDim.x + threadIdx.x;
    if (2 * i + 1 < nwords && w[2 * i + 1]) atomicOr(&d_is32, 1);
}

// ---------------------------------------------------------------- single-pass bucket fill
__global__ void k_fill(const void* __restrict__ ei, int E) {
    int e = blockIdx.x * blockDim.x + threadIdx.x;
    if (e >= E) return;
    int s, d;
    if (d_is32) {
        const int* p = (const int*)ei;
        s = __ldg(&p[e]); d = __ldg(&p[E + e]);
    } else {
        const long long* p = (const long long*)ei;
        s = (int)__ldg(&p[e]); d = (int)__ldg(&p[E + e]);
    }
    int pos = atomicAdd(&d_cnt[d], 1);
    d_csr[d * CAP + pos] = s;
}

// ---------------------------------------------------------------- transform1 (8x4 tile GEMM):
// dinv = rsqrt(cnt+1);  g1 = (x@W1)*dinv
// 256 threads: tx=tid&7 -> col quad, ty=tid>>3 -> rows ty+32i, i=0..7.
__global__ void k_transform1(const float* __restrict__ x,
                             const float* __restrict__ W1, int N) {
    __shared__ float xs[T1_BM * XST];   // 20 KB
    __shared__ float Ws[FEAT * HID];    // 16 KB

    int tid = threadIdx.x;
    for (int i = tid; i < FEAT * HID / 4; i += 256)
        ((float4*)Ws)[i] = ((const float4*)W1)[i];

    int row0 = blockIdx.x * T1_BM;
    int tx = tid & 7;
    int ty = tid >> 3;
    int c0 = tx * 4;

    float4 acc[8];
#pragma unroll
    for (int i = 0; i < 8; i++) acc[i] = make_float4(0.f, 0.f, 0.f, 0.f);

    for (int kb = 0; kb < FEAT; kb += T1_KC) {
        __syncthreads();
        // stage x chunk: 256 rows x 16 floats (4 vec4/row); coalesced
        for (int j = tid; j < T1_BM * (T1_KC / 4); j += 256) {
            int r = j >> 2;
            int cc = (j & 3) << 2;
            float4 v = make_float4(0.f, 0.f, 0.f, 0.f);
            if (row0 + r < N)
                v = *(const float4*)&x[(row0 + r) * FEAT + kb + cc];
            *(float4*)&xs[r * XST + cc] = v;
        }
        __syncthreads();

#pragma unroll
        for (int k = 0; k < T1_KC; k += 4) {
            float4 w0 = *(float4*)&Ws[(kb + k + 0) * HID + c0];
            float4 w1 = *(float4*)&Ws[(kb + k + 1) * HID + c0];
            float4 w2 = *(float4*)&Ws[(kb + k + 2) * HID + c0];
            float4 w3 = *(float4*)&Ws[(kb + k + 3) * HID + c0];
#pragma unroll
            for (int i = 0; i < 8; i++) {
                float4 xv = *(float4*)&xs[(ty + 32 * i) * XST + k];
                acc[i].x = fmaf(xv.x, w0.x, acc[i].x); acc[i].y = fmaf(xv.x, w0.y, acc[i].y);
                acc[i].z = fmaf(xv.x, w0.z, acc[i].z); acc[i].w = fmaf(xv.x, w0.w, acc[i].w);
                acc[i].x = fmaf(xv.y, w1.x, acc[i].x); acc[i].y = fmaf(xv.y, w1.y, acc[i].y);
                acc[i].z = fmaf(xv.y, w1.z, acc[i].z); acc[i].w = fmaf(xv.y, w1.w, acc[i].w);
                acc[i].x = fmaf(xv.z, w2.x, acc[i].x); acc[i].y = fmaf(xv.z, w2.y, acc[i].y);
                acc[i].z = fmaf(xv.z, w2.z, acc[i].z); acc[i].w = fmaf(xv.z, w2.w, acc[i].w);
                acc[i].x = fmaf(xv.w, w3.x, acc[i].x); acc[i].y = fmaf(xv.w, w3.y, acc[i].y);
                acc[i].z = fmaf(xv.w, w3.z, acc[i].z); acc[i].w = fmaf(xv.w, w3.w, acc[i].w);
            }
        }
    }

#pragma unroll
    for (int i = 0; i < 8; i++) {
        int row = row0 + ty + 32 * i;
        if (row < N) {
            float d = rsqrtf((float)__ldg(&d_cnt[row]) + 1.0f);
            if (tx == 0) d_dinv[row] = d;
            float4 a = acc[i];
            a.x *= d; a.y *= d; a.z *= d; a.w *= d;
            *(float4*)&d_g1[row * HID + c0] = a;
        }
    }
}

// ---------------------------------------------------------------- quad-mode warp gather:
// lane = (egrp = lane>>3 -> edge-in-group-of-4, c0 = (lane&7)*4 -> col quad).
// Per 4 edges: 1 SHFL + 1 LDG.128 + 2 add.f32x2. Cross-group reduce at end,
// then a 1-warp smem transpose back to one-col-per-lane.
__device__ __forceinline__ float gather_row_q(const float* __restrict__ g,
                                              int row, int lane,
                                              float* __restrict__ swarp) {
    int egrp = lane >> 3;
    int c0 = (lane & 7) << 2;

    // self loop counted once (group 0 only); g row pre-scaled by dinv[row]
    ulonglong2 acc = *(const ulonglong2*)(g + row * HID + c0);
    if (egrp != 0) { acc.x = 0ull; acc.y = 0ull; }

    int cnt = __ldg(&d_cnt[row]);
    int base = row * CAP;
    int full = cnt & ~31;
    for (int e0 = 0; e0 < full; e0 += 32) {
        int idx = __ldg(&d_csr[base + e0 + lane]);
#pragma unroll
        for (int k = 0; k < 8; k++) {
            int s = __shfl_sync(0xffffffffu, idx, (k << 2) + egrp);
            ulonglong2 v = *(const ulonglong2*)(g + s * HID + c0);
            asm("add.rn.f32x2 %0, %0, %1;" : "+l"(acc.x) : "l"(v.x));
            asm("add.rn.f32x2 %0, %0, %1;" : "+l"(acc.y) : "l"(v.y));
        }
    }
    int m = cnt - full;
    if (m) {
        int idx = __ldg(&d_csr[base + full + min(lane, m - 1)]);
#pragma unroll
        for (int k = 0; k < 8; k++) {
            if ((k << 2) >= m) break;  // uniform (m is warp-uniform)
            int e = (k << 2) + egrp;
            int s = __shfl_sync(0xffffffffu, idx, min(e, m - 1));
            if (e < m) {
                ulonglong2 v = *(const ulonglong2*)(g + s * HID + c0);
                asm("add.rn.f32x2 %0, %0, %1;" : "+l"(acc.x) : "l"(v.x));
                asm("add.rn.f32x2 %0, %0, %1;" : "+l"(acc.y) : "l"(v.y));
            }
        }
    }

    float ax, ay, az, aw;
    asm("mov.b64 {%0, %1}, %2;" : "=f"(ax), "=f"(ay) : "l"(acc.x));
    asm("mov.b64 {%0, %1}, %2;" : "=f"(az), "=f"(aw) : "l"(acc.y));
    // reduce across the 4 edge-groups (lanes xor 8, xor 16)
#pragma unroll
    for (int d = 8; d <= 16; d <<= 1) {
        ax += __shfl_xor_sync(0xffffffffu, ax, d);
        ay += __shfl_xor_sync(0xffffffffu, ay, d);
        az += __shfl_xor_sync(0xffffffffu, az, d);
        aw += __shfl_xor_sync(0xffffffffu, aw, d);
    }
    // transpose quad-per-lane -> scalar-per-lane via warp-private smem
    if (lane < 8) *(float4*)(swarp + c0) = make_float4(ax, ay, az, aw);
    __syncwarp();
    return swarp[lane];
}

// ---------------------------------------------------------------- gather1 + relu + transform2 fused:
// h1 = relu(dinv*(sum g1)+b1);  g2 = (h1@W2)*dinv
__global__ void k_gather_mid(const float* __restrict__ b1,
                             const float* __restrict__ W2, int N) {
    __shared__ float Ws[HID * HID];        // 4 KB
    __shared__ float sbuf[8 * HID];        // 1 KB (per-warp transpose)
    for (int i = threadIdx.x; i < HID * HID; i += blockDim.x) Ws[i] = W2[i];
    __syncthreads();

    int warp = (blockIdx.x * blockDim.x + threadIdx.x) >> 5;
    int lane = threadIdx.x & 31;
    if (warp >= N) return;
    int row = warp;

    float acc = gather_row_q(d_g1, row, lane, sbuf + (threadIdx.x >> 5) * HID);
    float d = __ldg(&d_dinv[row]);
    float t = fmaxf(fmaf(acc, d, b1[lane]), 0.f);  // h1[row][lane]

    float o = 0.f;
#pragma unroll
    for (int k = 0; k < HID; k++) {
        float tk = __shfl_sync(0xffffffffu, t, k);
        o = fmaf(tk, Ws[k * HID + lane], o);
    }
    d_g2[row * HID + lane] = o * d;
}

// ---------------------------------------------------------------- gather2 + relu + head fused:
// h2 = relu(dinv*(sum g2)+b2);  out = h2@Wout + bout
__global__ void k_gather_final(const float* __restrict__ b2,
                               const float* __restrict__ Wout,
                               const float* __restrict__ bout,
                               float* __restrict__ out, int N) {
    __shared__ float Ws[HID * NOUT];       // 8 KB
    __shared__ float sbuf[8 * HID];        // 1 KB
    for (int i = threadIdx.x; i < HID * NOUT; i += blockDim.x) Ws[i] = Wout[i];
    __syncthreads();

    int warp = (blockIdx.x * blockDim.x + threadIdx.x) >> 5;
    int lane = threadIdx.x & 31;
    if (warp >= N) return;
    int row = warp;

    float acc = gather_row_q(d_g2, row, lane, sbuf + (threadIdx.x >> 5) * HID);
    float d = __ldg(&d_dinv[row]);
    float t = fmaxf(fmaf(acc, d, b2[lane]), 0.f);  // h2[row][lane]

    float acc0 = bout[lane];
    float acc1 = bout[lane + 32];
#pragma unroll
    for (int k = 0; k < HID; k++) {
        float tk = __shfl_sync(0xffffffffu, t, k);
        acc0 = fmaf(tk, Ws[k * NOUT + lane], acc0);
        acc1 = fmaf(tk, Ws[k * NOUT + lane + 32], acc1);
    }
    out[row * NOUT + lane] = acc0;
    out[row * NOUT + lane + 32] = acc1;
}

// ---------------------------------------------------------------- launch
extern "C" void kernel_launch(void* const* d_in, const int* in_sizes, int n_in,
                              void* d_out, int out_size) {
    const float* x = (const float*)d_in[0];
    const void* ei = d_in[1];
    const float* W1 = (const float*)d_in[2];
    const float* b1 = (const float*)d_in[3];
    const float* W2 = (const float*)d_in[4];
    const float* b2 = (const float*)d_in[5];
    const float* Wout = (const float*)d_in[6];
    const float* bout = (const float*)d_in[7];
    float* out = (float*)d_out;

    int N = in_sizes[0] / FEAT;     // 50000
    int E = in_sizes[1] / 2;        // 1600000

    const int TB = 256;
    // bucketed CSR build (single pass; no histogram, no scan)
    k_init<<<(N + TB - 1) / TB, TB>>>(N);
    k_detect<<<256, TB>>>((const int*)ei, 2 * E);
    k_fill<<<(E + TB - 1) / TB, TB>>>(ei, E);
    // layer 1 transform (+ dinv), 8x4 register-blocked GEMM
    k_transform1<<<(N + T1_BM - 1) / T1_BM, 256>>>(x, W1, N);
    // layer 1 aggregate + layer 2 transform (fused)
    k_gather_mid<<<(N * 32 + TB - 1) / TB, TB>>>(b1, W2, N);
    // layer 2 aggregate + head (fused)
    k_gather_final<<<(N * 32 + TB - 1) / TB, TB>>>(b2, Wout, bout, out, N);
}

// round 11
// speedup vs baseline: 1.1545x; 1.1545x over previous
#include <cuda_runtime.h>
#include <cuda_bf16.h>
#include <stdint.h>

#define MAXN 50000
#define MAXE 1600000
#define FEAT 128
#define HID 32
#define NOUT 64
#define CAP 160    // bucket capacity; deg ~ Poisson(32), P(deg>=160) ~ 0

#define T1_BM 128  // rows per block in transform1
#define T1_KC 32   // k-chunk (transposed staging)

// Scratch (device globals; allocation is forbidden).
__device__ int    d_is32;                 // 1 if edge_index is int32
__device__ int    d_cnt[MAXN];            // in-degree (no self loop)
__device__ int    d_csr[MAXN * CAP];      // bucketed: src ids for dst=i at [i*CAP ...]
__device__ float  d_dinv[MAXN];           // rsqrt(deg+1)
__device__ float  d_g1[MAXN * HID];       // (x@W1)*dinv
__device__ float  d_g2[MAXN * HID];       // (h1@W2)*dinv

// ---------------------------------------------------------------- init + dtype detect
__global__ void k_init(int N) {
    int i = blockIdx.x * blockDim.x + threadIdx.x;
    if (i < N) d_cnt[i] = 0;
    if (i == 0) d_is32 = 0;
}

// Sample first 64K words: int64 indices < 2^31 have all-zero odd 32-bit words.
__global__ void k_detect(const int* __restrict__ w, int nwords) {
    int i = blockIdx.x * blockDim.x + threadIdx.x;
    if (2 * i + 1 < nwords && w[2 * i + 1]) atomicOr(&d_is32, 1);
}

// ---------------------------------------------------------------- single-pass bucket fill
__global__ void k_fill(const void* __restrict__ ei, int E) {
    int e = blockIdx.x * blockDim.x + threadIdx.x;
    if (e >= E) return;
    int s, d;
    if (d_is32) {
        const int* p = (const int*)ei;
        s = __ldg(&p[e]); d = __ldg(&p[E + e]);
    } else {
        const long long* p = (const long long*)ei;
        s = (int)__ldg(&p[e]); d = (int)__ldg(&p[E + e]);
    }
    int pos = atomicAdd(&d_cnt[d], 1);
    d_csr[d * CAP + pos] = s;
}

// ---------------------------------------------------------------- transform1 (4x4 tile, transposed xs):
// dinv = rsqrt(cnt+1);  g1 = (x@W1)*dinv
// 256 threads: tx=tid&7 -> col quad c0=tx*4; ty=tid>>3 -> rows r0=ty*4..+3.
// xs[k][r] layout: per k one LDS.128 yields this thread's 4 rows, conflict-free.
__global__ void k_transform1(const float* __restrict__ x,
                             const float* __restrict__ W1, int N) {
    __shared__ float xs[T1_KC * T1_BM];   // 16 KB (transposed chunk)
    __shared__ float Ws[FEAT * HID];      // 16 KB

    int tid = threadIdx.x;
    for (int i = tid; i < FEAT * HID / 4; i += 256)
        ((float4*)Ws)[i] = ((const float4*)W1)[i];

    int row0 = blockIdx.x * T1_BM;
    int tx = tid & 7;
    int ty = tid >> 3;
    int c0 = tx * 4;
    int r0 = ty * 4;

    float4 acc[4];
#pragma unroll
    for (int i = 0; i < 4; i++) acc[i] = make_float4(0.f, 0.f, 0.f, 0.f);

    // staging assignment: thread handles row sr, quads q0..q0+3 of the chunk
    int sr = tid >> 1;
    int q0 = (tid & 1) * 4;
    bool ok = (row0 + sr) < N;

    for (int kb = 0; kb < FEAT; kb += T1_KC) {
        __syncthreads();
        const float4* xr = (const float4*)&x[(row0 + sr) * FEAT + kb];
#pragma unroll
        for (int i = 0; i < 4; i++) {
            float4 v = ok ? __ldg(&xr[q0 + i]) : make_float4(0.f, 0.f, 0.f, 0.f);
            int k = (q0 + i) * 4;
            xs[(k + 0) * T1_BM + sr] = v.x;
            xs[(k + 1) * T1_BM + sr] = v.y;
            xs[(k + 2) * T1_BM + sr] = v.z;
            xs[(k + 3) * T1_BM + sr] = v.w;
        }
        __syncthreads();

#pragma unroll
        for (int k = 0; k < T1_KC; k++) {
            float4 xv = *(float4*)&xs[k * T1_BM + r0];       // 4 rows at k
            float4 w  = *(float4*)&Ws[(kb + k) * HID + c0];  // 4 cols at k
            acc[0].x = fmaf(xv.x, w.x, acc[0].x); acc[0].y = fmaf(xv.x, w.y, acc[0].y);
            acc[0].z = fmaf(xv.x, w.z, acc[0].z); acc[0].w = fmaf(xv.x, w.w, acc[0].w);
            acc[1].x = fmaf(xv.y, w.x, acc[1].x); acc[1].y = fmaf(xv.y, w.y, acc[1].y);
            acc[1].z = fmaf(xv.y, w.z, acc[1].z); acc[1].w = fmaf(xv.y, w.w, acc[1].w);
            acc[2].x = fmaf(xv.z, w.x, acc[2].x); acc[2].y = fmaf(xv.z, w.y, acc[2].y);
            acc[2].z = fmaf(xv.z, w.z, acc[2].z); acc[2].w = fmaf(xv.z, w.w, acc[2].w);
            acc[3].x = fmaf(xv.w, w.x, acc[3].x); acc[3].y = fmaf(xv.w, w.y, acc[3].y);
            acc[3].z = fmaf(xv.w, w.z, acc[3].z); acc[3].w = fmaf(xv.w, w.w, acc[3].w);
        }
    }

#pragma unroll
    for (int i = 0; i < 4; i++) {
        int row = row0 + r0 + i;
        if (row < N) {
            float d = rsqrtf((float)__ldg(&d_cnt[row]) + 1.0f);
            if (tx == 0) d_dinv[row] = d;
            float4 a = acc[i];
            a.x *= d; a.y *= d; a.z *= d; a.w *= d;
            *(float4*)&d_g1[row * HID + c0] = a;
        }
    }
}

// ---------------------------------------------------------------- quad-mode warp gather:
// lane = (egrp = lane>>3 -> edge-in-group-of-4, c0 = (lane&7)*4 -> col quad).
// Per 4 edges: 1 SHFL + 1 LDG.128 + 2 add.f32x2. Cross-group reduce at end,
// then a 1-warp smem transpose back to one-col-per-lane.
__device__ __forceinline__ float gather_row_q(const float* __restrict__ g,
                                              int row, int lane,
                                              float* __restrict__ swarp) {
    int egrp = lane >> 3;
    int c0 = (lane & 7) << 2;

    // self loop counted once (group 0 only); g row pre-scaled by dinv[row]
    ulonglong2 acc = *(const ulonglong2*)(g + row * HID + c0);
    if (egrp != 0) { acc.x = 0ull; acc.y = 0ull; }

    int cnt = __ldg(&d_cnt[row]);
    int base = row * CAP;
    int full = cnt & ~31;
    for (int e0 = 0; e0 < full; e0 += 32) {
        int idx = __ldg(&d_csr[base + e0 + lane]);
#pragma unroll
        for (int k = 0; k < 8; k++) {
            int s = __shfl_sync(0xffffffffu, idx, (k << 2) + egrp);
            ulonglong2 v = *(const ulonglong2*)(g + s * HID + c0);
            asm("add.rn.f32x2 %0, %0, %1;" : "+l"(acc.x) : "l"(v.x));
            asm("add.rn.f32x2 %0, %0, %1;" : "+l"(acc.y) : "l"(v.y));
        }
    }
    int m = cnt - full;
    if (m) {
        int idx = __ldg(&d_csr[base + full + min(lane, m - 1)]);
#pragma unroll
        for (int k = 0; k < 8; k++) {
            if ((k << 2) >= m) break;  // uniform (m is warp-uniform)
            int e = (k << 2) + egrp;
            int s = __shfl_sync(0xffffffffu, idx, min(e, m - 1));
            if (e < m) {
                ulonglong2 v = *(const ulonglong2*)(g + s * HID + c0);
                asm("add.rn.f32x2 %0, %0, %1;" : "+l"(acc.x) : "l"(v.x));
                asm("add.rn.f32x2 %0, %0, %1;" : "+l"(acc.y) : "l"(v.y));
            }
        }
    }

    float ax, ay, az, aw;
    asm("mov.b64 {%0, %1}, %2;" : "=f"(ax), "=f"(ay) : "l"(acc.x));
    asm("mov.b64 {%0, %1}, %2;" : "=f"(az), "=f"(aw) : "l"(acc.y));
    // reduce across the 4 edge-groups (lanes xor 8, xor 16)
#pragma unroll
    for (int d = 8; d <= 16; d <<= 1) {
        ax += __shfl_xor_sync(0xffffffffu, ax, d);
        ay += __shfl_xor_sync(0xffffffffu, ay, d);
        az += __shfl_xor_sync(0xffffffffu, az, d);
        aw += __shfl_xor_sync(0xffffffffu, aw, d);
    }
    // transpose quad-per-lane -> scalar-per-lane via warp-private smem
    if (lane < 8) *(float4*)(swarp + c0) = make_float4(ax, ay, az, aw);
    __syncwarp();
    return swarp[lane];
}

// ---------------------------------------------------------------- gather1 + relu + transform2 fused:
// h1 = relu(dinv*(sum g1)+b1);  g2 = (h1@W2)*dinv
__global__ void k_gather_mid(const float* __restrict__ b1,
                             const float* __restrict__ W2, int N) {
    __shared__ float Ws[HID * HID];        // 4 KB
    __shared__ float sbuf[8 * HID];        // 1 KB (per-warp transpose)
    for (int i = threadIdx.x; i < HID * HID; i += blockDim.x) Ws[i] = W2[i];
    __syncthreads();

    int warp = (blockIdx.x * blockDim.x + threadIdx.x) >> 5;
    int lane = threadIdx.x & 31;
    if (warp >= N) return;
    int row = warp;

    float acc = gather_row_q(d_g1, row, lane, sbuf + (threadIdx.x >> 5) * HID);
    float d = __ldg(&d_dinv[row]);
    float t = fmaxf(fmaf(acc, d, b1[lane]), 0.f);  // h1[row][lane]

    float o = 0.f;
#pragma unroll
    for (int k = 0; k < HID; k++) {
        float tk = __shfl_sync(0xffffffffu, t, k);
        o = fmaf(tk, Ws[k * HID + lane], o);
    }
    d_g2[row * HID + lane] = o * d;
}

// ---------------------------------------------------------------- gather2 + relu + head fused:
// h2 = relu(dinv*(sum g2)+b2);  out = h2@Wout + bout
__global__ void k_gather_final(const float* __restrict__ b2,
                               const float* __restrict__ Wout,
                               const float* __restrict__ bout,
                               float* __restrict__ out, int N) {
    __shared__ float Ws[HID * NOUT];       // 8 KB
    __shared__ float sbuf[8 * HID];        // 1 KB
    for (int i = threadIdx.x; i < HID * NOUT; i += blockDim.x) Ws[i] = Wout[i];
    __syncthreads();

    int warp = (blockIdx.x * blockDim.x + threadIdx.x) >> 5;
    int lane = threadIdx.x & 31;
    if (warp >= N) return;
    int row = warp;

    float acc = gather_row_q(d_g2, row, lane, sbuf + (threadIdx.x >> 5) * HID);
    float d = __ldg(&d_dinv[row]);
    float t = fmaxf(fmaf(acc, d, b2[lane]), 0.f);  // h2[row][lane]

    float acc0 = bout[lane];
    float acc1 = bout[lane + 32];
#pragma unroll
    for (int k = 0; k < HID; k++) {
        float tk = __shfl_sync(0xffffffffu, t, k);
        acc0 = fmaf(tk, Ws[k * NOUT + lane], acc0);
        acc1 = fmaf(tk, Ws[k * NOUT + lane + 32], acc1);
    }
    out[row * NOUT + lane] = acc0;
    out[row * NOUT + lane + 32] = acc1;
}

// ---------------------------------------------------------------- launch
extern "C" void kernel_launch(void* const* d_in, const int* in_sizes, int n_in,
                              void* d_out, int out_size) {
    const float* x = (const float*)d_in[0];
    const void* ei = d_in[1];
    const float* W1 = (const float*)d_in[2];
    const float* b1 = (const float*)d_in[3];
    const float* W2 = (const float*)d_in[4];
    const float* b2 = (const float*)d_in[5];
    const float* Wout = (const float*)d_in[6];
    const float* bout = (const float*)d_in[7];
    float* out = (float*)d_out;

    int N = in_sizes[0] / FEAT;     // 50000
    int E = in_sizes[1] / 2;        // 1600000

    const int TB = 256;
    // bucketed CSR build (single pass; no histogram, no scan)
    k_init<<<(N + TB - 1) / TB, TB>>>(N);
    k_detect<<<256, TB>>>((const int*)ei, 2 * E);
    k_fill<<<(E + TB - 1) / TB, TB>>>(ei, E);
    // layer 1 transform (+ dinv), 4x4 register-blocked GEMM, transposed xs
    k_transform1<<<(N + T1_BM - 1) / T1_BM, 256>>>(x, W1, N);
    // layer 1 aggregate + layer 2 transform (fused)
    k_gather_mid<<<(N * 32 + TB - 1) / TB, TB>>>(b1, W2, N);
    // layer 2 aggregate + head (fused)
    k_gather_final<<<(N * 32 + TB - 1) / TB, TB>>>(b2, Wout, bout, out, N);
}

// round 12
// speedup vs baseline: 1.2016x; 1.0408x over previous
#include <cuda_runtime.h>
#include <cuda_fp16.h>
#include <stdint.h>

#define MAXN 50000
#define MAXE 1600000
#define FEAT 128
#define HID 32
#define NOUT 64
#define CAP 160    // bucket capacity; deg ~ Poisson(32), P(deg>=160) ~ 0

#define T1_BM 128  // rows per block in transform1
#define T1_KC 32   // k-chunk (transposed staging)

// Scratch (device globals; allocation is forbidden).
// d_is32 is zero-initialized and sticky: only ever OR'd to 1; deterministic per input.
__device__ int    d_is32;                 // 1 if edge_index is int32
__device__ int    d_cnt[MAXN];            // in-degree (no self loop)
__device__ int    d_csr[MAXN * CAP];      // bucketed: src ids for dst=i at [i*CAP ...]
__device__ float  d_dinv[MAXN];           // rsqrt(deg+1)
__device__ __half d_g1[MAXN * HID];       // (x@W1)*dinv, fp16 messages
__device__ __half d_g2[MAXN * HID];       // (h1@W2)*dinv, fp16 messages

// ---------------------------------------------------------------- prelude: zero cnt + dtype detect
// int64 indices < 2^31 have all-zero odd 32-bit words; int32 makes them nonzero a.s.
__global__ void k_prelude(const int* __restrict__ w, int N) {
    int i = blockIdx.x * blockDim.x + threadIdx.x;
    if (i < N) d_cnt[i] = 0;
    if (__ldg(&w[2 * i + 1])) atomicOr(&d_is32, 1);  // samples ~50K words, < 2E words total
}

// ---------------------------------------------------------------- single-pass bucket fill
__global__ void k_fill(const void* __restrict__ ei, int E) {
    int e = blockIdx.x * blockDim.x + threadIdx.x;
    if (e >= E) return;
    int s, d;
    if (d_is32) {
        const int* p = (const int*)ei;
        s = __ldg(&p[e]); d = __ldg(&p[E + e]);
    } else {
        const long long* p = (const long long*)ei;
        s = (int)__ldg(&p[e]); d = (int)__ldg(&p[E + e]);
    }
    int pos = atomicAdd(&d_cnt[d], 1);
    d_csr[d * CAP + pos] = s;
}

// ---------------------------------------------------------------- transform1 (4x4 tile, transposed xs,
// register-prefetch pipelined): dinv = rsqrt(cnt+1);  g1 = fp16((x@W1)*dinv)
__global__ void k_transform1(const float* __restrict__ x,
                             const float* __restrict__ W1, int N) {
    __shared__ float xs[T1_KC * T1_BM];   // 16 KB (transposed chunk)
    __shared__ float Ws[FEAT * HID];      // 16 KB

    int tid = threadIdx.x;
    for (int i = tid; i < FEAT * HID / 4; i += 256)
        ((float4*)Ws)[i] = ((const float4*)W1)[i];

    int row0 = blockIdx.x * T1_BM;
    int tx = tid & 7;
    int ty = tid >> 3;
    int c0 = tx * 4;
    int r0 = ty * 4;

    float4 acc[4];
#pragma unroll
    for (int i = 0; i < 4; i++) acc[i] = make_float4(0.f, 0.f, 0.f, 0.f);

    // staging assignment: thread stages row sr, quads q0..q0+3 of each chunk
    int sr = tid >> 1;
    int q0 = (tid & 1) * 4;
    bool ok = (row0 + sr) < N;
    const float4* xr = (const float4*)&x[(row0 + sr) * FEAT];

    float4 pre[4];
#pragma unroll
    for (int i = 0; i < 4; i++)
        pre[i] = ok ? __ldg(&xr[q0 + i]) : make_float4(0.f, 0.f, 0.f, 0.f);

    for (int kb = 0; kb < FEAT; kb += T1_KC) {
        __syncthreads();   // previous chunk's readers done
#pragma unroll
        for (int i = 0; i < 4; i++) {
            int k = (q0 + i) * 4;
            xs[(k + 0) * T1_BM + sr] = pre[i].x;
            xs[(k + 1) * T1_BM + sr] = pre[i].y;
            xs[(k + 2) * T1_BM + sr] = pre[i].z;
            xs[(k + 3) * T1_BM + sr] = pre[i].w;
        }
        __syncthreads();

        if (kb + T1_KC < FEAT) {  // prefetch next chunk; latency hidden by FMAs below
            const float4* xn = xr + (kb + T1_KC) / 4;
#pragma unroll
            for (int i = 0; i < 4; i++)
                pre[i] = ok ? __ldg(&xn[q0 + i]) : make_float4(0.f, 0.f, 0.f, 0.f);
        }

#pragma unroll
        for (int k = 0; k < T1_KC; k++) {
            float4 xv = *(float4*)&xs[k * T1_BM + r0];       // 4 rows at k
            float4 w  = *(float4*)&Ws[(kb + k) * HID + c0];  // 4 cols at k
            acc[0].x = fmaf(xv.x, w.x, acc[0].x); acc[0].y = fmaf(xv.x, w.y, acc[0].y);
            acc[0].z = fmaf(xv.x, w.z, acc[0].z); acc[0].w = fmaf(xv.x, w.w, acc[0].w);
            acc[1].x = fmaf(xv.y, w.x, acc[1].x); acc[1].y = fmaf(xv.y, w.y, acc[1].y);
            acc[1].z = fmaf(xv.y, w.z, acc[1].z); acc[1].w = fmaf(xv.y, w.w, acc[1].w);
            acc[2].x = fmaf(xv.z, w.x, acc[2].x); acc[2].y = fmaf(xv.z, w.y, acc[2].y);
            acc[2].z = fmaf(xv.z, w.z, acc[2].z); acc[2].w = fmaf(xv.z, w.w, acc[2].w);
            acc[3].x = fmaf(xv.w, w.x, acc[3].x); acc[3].y = fmaf(xv.w, w.y, acc[3].y);
            acc[3].z = fmaf(xv.w, w.z, acc[3].z); acc[3].w = fmaf(xv.w, w.w, acc[3].w);
        }
    }

#pragma unroll
    for (int i = 0; i < 4; i++) {
        int row = row0 + r0 + i;
        if (row < N) {
            float d = rsqrtf((float)__ldg(&d_cnt[row]) + 1.0f);
            if (tx == 0) d_dinv[row] = d;
            float4 a = acc[i];
            __half2 h01 = __floats2half2_rn(a.x * d, a.y * d);
            __half2 h23 = __floats2half2_rn(a.z * d, a.w * d);
            uint2 pk;
            pk.x = *(unsigned*)&h01;
            pk.y = *(unsigned*)&h23;
            *(uint2*)&d_g1[row * HID + c0] = pk;
        }
    }
}

// ---------------------------------------------------------------- quad-mode warp gather (fp16 rows):
// lane = (egrp = lane>>3 -> edge-in-group-of-4, c0 = (lane&7)*4 -> col quad, 8B LDG.64).
// fp32 accumulation. Cross-group reduce + 1-warp smem transpose at the end.
__device__ __forceinline__ float gather_row_q(const __half* __restrict__ g,
                                              int row, int lane,
                                              float* __restrict__ swarp) {
    int egrp = lane >> 3;
    int c0 = (lane & 7) << 2;

    float ax = 0.f, ay = 0.f, az = 0.f, aw = 0.f;
    if (egrp == 0) {  // self loop counted once; g row pre-scaled by dinv[row]
        uint2 sv = *(const uint2*)(g + row * HID + c0);
        float2 f0 = __half22float2(*(__half2*)&sv.x);
        float2 f1 = __half22float2(*(__half2*)&sv.y);
        ax = f0.x; ay = f0.y; az = f1.x; aw = f1.y;
    }

    int cnt = __ldg(&d_cnt[row]);
    int base = row * CAP;
    int full = cnt & ~31;
    for (int e0 = 0; e0 < full; e0 += 32) {
        int idx = __ldg(&d_csr[base + e0 + lane]);
#pragma unroll
        for (int k = 0; k < 8; k++) {
            int s = __shfl_sync(0xffffffffu, idx, (k << 2) + egrp);
            uint2 v = *(const uint2*)(g + s * HID + c0);
            float2 p = __half22float2(*(__half2*)&v.x);
            float2 q = __half22float2(*(__half2*)&v.y);
            ax += p.x; ay += p.y; az += q.x; aw += q.y;
        }
    }
    int m = cnt - full;
    if (m) {
        int idx = __ldg(&d_csr[base + full + min(lane, m - 1)]);
#pragma unroll
        for (int k = 0; k < 8; k++) {
            if ((k << 2) >= m) break;  // uniform (m is warp-uniform)
            int e = (k << 2) + egrp;
            int s = __shfl_sync(0xffffffffu, idx, min(e, m - 1));
            if (e < m) {
                uint2 v = *(const uint2*)(g + s * HID + c0);
                float2 p = __half22float2(*(__half2*)&v.x);
                float2 q = __half22float2(*(__half2*)&v.y);
                ax += p.x; ay += p.y; az += q.x; aw += q.y;
            }
        }
    }

    // reduce across the 4 edge-groups (lanes xor 8, xor 16)
#pragma unroll
    for (int d = 8; d <= 16; d <<= 1) {
        ax += __shfl_xor_sync(0xffffffffu, ax, d);
        ay += __shfl_xor_sync(0xffffffffu, ay, d);
        az += __shfl_xor_sync(0xffffffffu, az, d);
        aw += __shfl_xor_sync(0xffffffffu, aw, d);
    }
    // transpose quad-per-lane -> scalar-per-lane via warp-private smem
    if (lane < 8) *(float4*)(swarp + c0) = make_float4(ax, ay, az, aw);
    __syncwarp();
    return swarp[lane];
}

// ---------------------------------------------------------------- gather1 + relu + transform2 fused:
// h1 = relu(dinv*(sum g1)+b1);  g2 = fp16((h1@W2)*dinv)
__global__ void k_gather_mid(const float* __restrict__ b1,
                             const float* __restrict__ W2, int N) {
    __shared__ float Ws[HID * HID];        // 4 KB
    __shared__ float sbuf[8 * HID];        // 1 KB (per-warp transpose)
    for (int i = threadIdx.x; i < HID * HID; i += blockDim.x) Ws[i] = W2[i];
    __syncthreads();

    int warp = (blockIdx.x * blockDim.x + threadIdx.x) >> 5;
    int lane = threadIdx.x & 31;
    if (warp >= N) return;
    int row = warp;

    float acc = gather_row_q(d_g1, row, lane, sbuf + (threadIdx.x >> 5) * HID);
    float d = __ldg(&d_dinv[row]);
    float t = fmaxf(fmaf(acc, d, b1[lane]), 0.f);  // h1[row][lane]

    float o = 0.f;
#pragma unroll
    for (int k = 0; k < HID; k++) {
        float tk = __shfl_sync(0xffffffffu, t, k);
        o = fmaf(tk, Ws[k * HID + lane], o);
    }
    d_g2[row * HID + lane] = __float2half_rn(o * d);
}

// ---------------------------------------------------------------- gather2 + relu + head fused:
// h2 = relu(dinv*(sum g2)+b2);  out = h2@Wout + bout
__global__ void k_gather_final(const float* __restrict__ b2,
                               const float* __restrict__ Wout,
                               const float* __restrict__ bout,
                               float* __restrict__ out, int N) {
    __shared__ float Ws[HID * NOUT];       // 8 KB
    __shared__ float sbuf[8 * HID];        // 1 KB
    for (int i = threadIdx.x; i < HID * NOUT; i += blockDim.x) Ws[i] = Wout[i];
    __syncthreads();

    int warp = (blockIdx.x * blockDim.x + threadIdx.x) >> 5;
    int lane = threadIdx.x & 31;
    if (warp >= N) return;
    int row = warp;

    float acc = gather_row_q(d_g2, row, lane, sbuf + (threadIdx.x >> 5) * HID);
    float d = __ldg(&d_dinv[row]);
    float t = fmaxf(fmaf(acc, d, b2[lane]), 0.f);  // h2[row][lane]

    float acc0 = bout[lane];
    float acc1 = bout[lane + 32];
#pragma unroll
    for (int k = 0; k < HID; k++) {
        float tk = __shfl_sync(0xffffffffu, t, k);
        acc0 = fmaf(tk, Ws[k * NOUT + lane], acc0);
        acc1 = fmaf(tk, Ws[k * NOUT + lane + 32], acc1);
    }
    out[row * NOUT + lane] = acc0;
    out[row * NOUT + lane + 32] = acc1;
}

// ---------------------------------------------------------------- launch
extern "C" void kernel_launch(void* const* d_in, const int* in_sizes, int n_in,
                              void* d_out, int out_size) {
    const float* x = (const float*)d_in[0];
    const void* ei = d_in[1];
    const float* W1 = (const float*)d_in[2];
    const float* b1 = (const float*)d_in[3];
    const float* W2 = (const float*)d_in[4];
    const float* b2 = (const float*)d_in[5];
    const float* Wout = (const float*)d_in[6];
    const float* bout = (const float*)d_in[7];
    float* out = (float*)d_out;

    int N = in_sizes[0] / FEAT;     // 50000
    int E = in_sizes[1] / 2;        // 1600000

    const int TB = 256;
    // prelude (zero cnt + dtype detect) + bucketed CSR build
    k_prelude<<<(N + TB - 1) / TB, TB>>>((const int*)ei, N);
    k_fill<<<(E + TB - 1) / TB, TB>>>(ei, E);
    // layer 1 transform (+ dinv), 4x4 tile, register-prefetch pipelined
    k_transform1<<<(N + T1_BM - 1) / T1_BM, 256>>>(x, W1, N);
    // layer 1 aggregate + layer 2 transform (fused)
    k_gather_mid<<<(N * 32 + TB - 1) / TB, TB>>>(b1, W2, N);
    // layer 2 aggregate + head (fused)
    k_gather_final<<<(N * 32 + TB - 1) / TB, TB>>>(b2, Wout, bout, out, N);
}